// round 1
// baseline (speedup 1.0000x reference)
#include <cuda_runtime.h>
#include <cuda_bf16.h>

// ---------------------------------------------------------------------------
// Problem constants
// ---------------------------------------------------------------------------
#define BATCH 4
#define SEQ   4096
#define DM    512
#define DK    32
#define BS_ROWS (BATCH * SEQ)           // 16384
static const float INV_DK = 0.17677669529663687f;   // 1/sqrt(32) in fp32
#define NINF_F (-1e24f)

// ---------------------------------------------------------------------------
// Scratch (static device globals; allocations are forbidden)
// ---------------------------------------------------------------------------
static __device__ int   g_mask_mode;                        // 0 f32, 1 i32, 2 bf16, 3 u8
static __device__ float g_q[BS_ROWS * DK];                  // 2 MB
static __device__ float g_k[BS_ROWS * DK];                  // 2 MB
static __device__ float g_crow[BS_ROWS];                    // padded-key score per query row
static __device__ float g_padf[BS_ROWS];                    // key padding flag as float
static __device__ float g_v[(size_t)BS_ROWS * DM];          // 32 MB
static __device__ float g_h[(size_t)BS_ROWS * DM];          // 32 MB (attn out, then FFN out)
static __device__ float g_z[(size_t)BS_ROWS * DM];          // 32 MB
static __device__ float g_scores[(size_t)BATCH * SEQ * SEQ];// 256 MB (scores -> probs in place)

// ---------------------------------------------------------------------------
// Mask dtype handling
// ---------------------------------------------------------------------------
__device__ __forceinline__ bool mask_true(const void* p, long i, int mode)
{
    if (mode == 0) return ((const float*)p)[i] != 0.0f;
    if (mode == 1) return ((const int*)p)[i] != 0;
    if (mode == 2) return ((const unsigned short*)p)[i] != 0;
    return ((const unsigned char*)p)[i] != 0;
}

__global__ void detect_mask_kernel(const void* __restrict__ am)
{
    if (threadIdx.x != 0 || blockIdx.x != 0) return;
    const unsigned int* w = (const unsigned int*)am;
    bool f32ok = true, i32ok = true, bf16ok = true;
    for (int i = 0; i < 1024; i++) {
        unsigned int v = w[i];
        if (!(v == 0u || v == 0x3F800000u)) f32ok = false;
        if (!(v == 0u || v == 1u)) i32ok = false;
        unsigned int h0 = v & 0xFFFFu, h1 = v >> 16;
        if (!((h0 == 0u || h0 == 0x3F80u) && (h1 == 0u || h1 == 0x3F80u))) bf16ok = false;
    }
    int mode;
    if (f32ok) mode = 0;
    else if (i32ok) mode = 1;
    else if (bf16ok) mode = 2;
    else mode = 3;
    g_mask_mode = mode;
}

// ---------------------------------------------------------------------------
// Generic tiled fp32 GEMM: C[M,N] = A[M,K] @ B[K,N]   (row-major, batched by z)
// BM=BN=64, BK=16, 256 threads, 4x4 micro-tile.
// act: 0 = none, 1 = leaky_relu(0.01). bias optional (length N).
// Requires: M % 64 == 0, K % 16 == 0. N arbitrary (guarded), N % 4 == 0.
// ---------------------------------------------------------------------------
__global__ __launch_bounds__(256) void gemm_f32(
    const float* __restrict__ A, const float* __restrict__ B, float* __restrict__ C,
    int M, int N, int K, long sA, long sB, long sC,
    const float* __restrict__ bias, int act)
{
    A += (long)blockIdx.z * sA;
    B += (long)blockIdx.z * sB;
    C += (long)blockIdx.z * sC;

    __shared__ float As[16][64];
    __shared__ float Bs[16][64];

    const int tid = threadIdx.x;
    const int m0 = blockIdx.y * 64, n0 = blockIdx.x * 64;
    const int tx = tid & 15, ty = tid >> 4;
    const int arow = tid >> 2, ac = (tid & 3) * 4;
    const int brow = tid >> 4, bc = (tid & 15) * 4;

    float acc[4][4] = {};

    for (int k0 = 0; k0 < K; k0 += 16) {
        float4 av = *(const float4*)(A + (long)(m0 + arow) * K + k0 + ac);
        As[ac + 0][arow] = av.x;
        As[ac + 1][arow] = av.y;
        As[ac + 2][arow] = av.z;
        As[ac + 3][arow] = av.w;

        float4 bv;
        if (n0 + bc + 3 < N) {
            bv = *(const float4*)(B + (long)(k0 + brow) * N + n0 + bc);
        } else {
            bv.x = (n0 + bc + 0 < N) ? B[(long)(k0 + brow) * N + n0 + bc + 0] : 0.f;
            bv.y = (n0 + bc + 1 < N) ? B[(long)(k0 + brow) * N + n0 + bc + 1] : 0.f;
            bv.z = (n0 + bc + 2 < N) ? B[(long)(k0 + brow) * N + n0 + bc + 2] : 0.f;
            bv.w = (n0 + bc + 3 < N) ? B[(long)(k0 + brow) * N + n0 + bc + 3] : 0.f;
        }
        *(float4*)&Bs[brow][bc] = bv;

        __syncthreads();
#pragma unroll
        for (int kk = 0; kk < 16; kk++) {
            float4 a = *(const float4*)&As[kk][ty * 4];
            float4 b = *(const float4*)&Bs[kk][tx * 4];
            acc[0][0] += a.x * b.x; acc[0][1] += a.x * b.y; acc[0][2] += a.x * b.z; acc[0][3] += a.x * b.w;
            acc[1][0] += a.y * b.x; acc[1][1] += a.y * b.y; acc[1][2] += a.y * b.z; acc[1][3] += a.y * b.w;
            acc[2][0] += a.z * b.x; acc[2][1] += a.z * b.y; acc[2][2] += a.z * b.z; acc[2][3] += a.z * b.w;
            acc[3][0] += a.w * b.x; acc[3][1] += a.w * b.y; acc[3][2] += a.w * b.z; acc[3][3] += a.w * b.w;
        }
        __syncthreads();
    }

#pragma unroll
    for (int i = 0; i < 4; i++) {
        const int m = m0 + ty * 4 + i;
        float vv[4];
#pragma unroll
        for (int j = 0; j < 4; j++) {
            const int n = n0 + tx * 4 + j;
            float v = acc[i][j];
            if (bias && n < N) v += bias[n];
            if (act) v = (v > 0.f) ? v : 0.01f * v;
            vv[j] = v;
        }
        if (n0 + tx * 4 + 3 < N) {
            float4 o; o.x = vv[0]; o.y = vv[1]; o.z = vv[2]; o.w = vv[3];
            *(float4*)(C + (long)m * N + n0 + tx * 4) = o;
        } else {
#pragma unroll
            for (int j = 0; j < 4; j++) {
                const int n = n0 + tx * 4 + j;
                if (n < N) C[(long)m * N + n] = vv[j];
            }
        }
    }
}

// ---------------------------------------------------------------------------
// Per-row stats: c_i = rowsum(q) * (-1e24) * inv_dk ; pad flag as float
// ---------------------------------------------------------------------------
__global__ void rowstats_kernel(const void* __restrict__ pad)
{
    const int row = blockIdx.x * blockDim.x + threadIdx.x;
    if (row >= BS_ROWS) return;
    float s = 0.f;
#pragma unroll
    for (int d = 0; d < DK; d++) s += g_q[row * DK + d];
    g_crow[row] = s * NINF_F * INV_DK;
    g_padf[row] = mask_true(pad, row, g_mask_mode) ? 1.f : 0.f;
}

// ---------------------------------------------------------------------------
// Masked scores: S[b,q,k] = attn_mask ? -1e24 : (pad[k] ? c_q : (q.k)*inv_dk)
// 64x64 tile per block, fp32.
// ---------------------------------------------------------------------------
__global__ __launch_bounds__(256) void scores_kernel(const void* __restrict__ am)
{
    const int b = blockIdx.z;
    const int q0 = blockIdx.y * 64, k0 = blockIdx.x * 64;

    __shared__ float Qt[DK][64];
    __shared__ float Kt[DK][64];
    __shared__ float Cs[64];
    __shared__ float Ps[64];

    const int tid = threadIdx.x;
    const long rowq = (long)b * SEQ + q0;
    const long rowk = (long)b * SEQ + k0;

    for (int i = tid; i < 512; i += 256) {           // 64 rows x 8 float4
        const int r = i >> 3, c = (i & 7) * 4;
        float4 v = *(const float4*)(g_q + (rowq + r) * DK + c);
        Qt[c + 0][r] = v.x; Qt[c + 1][r] = v.y; Qt[c + 2][r] = v.z; Qt[c + 3][r] = v.w;
        float4 w = *(const float4*)(g_k + (rowk + r) * DK + c);
        Kt[c + 0][r] = w.x; Kt[c + 1][r] = w.y; Kt[c + 2][r] = w.z; Kt[c + 3][r] = w.w;
    }
    if (tid < 64) { Cs[tid] = g_crow[rowq + tid]; Ps[tid] = g_padf[rowk + tid]; }
    __syncthreads();

    const int tx = tid & 15, ty = tid >> 4;
    float acc[4][4] = {};
#pragma unroll
    for (int kk = 0; kk < DK; kk++) {
        float4 a = *(const float4*)&Qt[kk][ty * 4];
        float4 b2 = *(const float4*)&Kt[kk][tx * 4];
        acc[0][0] += a.x * b2.x; acc[0][1] += a.x * b2.y; acc[0][2] += a.x * b2.z; acc[0][3] += a.x * b2.w;
        acc[1][0] += a.y * b2.x; acc[1][1] += a.y * b2.y; acc[1][2] += a.y * b2.z; acc[1][3] += a.y * b2.w;
        acc[2][0] += a.z * b2.x; acc[2][1] += a.z * b2.y; acc[2][2] += a.z * b2.z; acc[2][3] += a.z * b2.w;
        acc[3][0] += a.w * b2.x; acc[3][1] += a.w * b2.y; acc[3][2] += a.w * b2.z; acc[3][3] += a.w * b2.w;
    }

    const int mode = g_mask_mode;
#pragma unroll
    for (int i = 0; i < 4; i++) {
        const int qi = q0 + ty * 4 + i;
        const long base = ((long)b * SEQ + qi) * SEQ;
        const float ci = Cs[ty * 4 + i];
#pragma unroll
        for (int j = 0; j < 4; j++) {
            const int kj = k0 + tx * 4 + j;
            float s = acc[i][j] * INV_DK;
            if (Ps[tx * 4 + j] != 0.f) s = ci;            // padded-key value (pre-softmax K mask)
            if (mask_true(am, base + kj, mode)) s = NINF_F; // attn mask overrides
            g_scores[base + kj] = s;
        }
    }
}

// ---------------------------------------------------------------------------
// Row softmax in place over SEQ=4096, one block (256 thr) per row.
// ---------------------------------------------------------------------------
__global__ __launch_bounds__(256) void softmax_kernel()
{
    const long row = (long)blockIdx.y * SEQ + blockIdx.x;
    float* p = g_scores + row * SEQ;
    const int tid = threadIdx.x;
    const int lane = tid & 31, wid = tid >> 5;
    __shared__ float red[8];

    float v[16];
#pragma unroll
    for (int i = 0; i < 16; i++) v[i] = p[tid + i * 256];

    float m = -3.4e38f;
#pragma unroll
    for (int i = 0; i < 16; i++) m = fmaxf(m, v[i]);
#pragma unroll
    for (int o = 16; o > 0; o >>= 1) m = fmaxf(m, __shfl_xor_sync(0xFFFFFFFFu, m, o));
    if (lane == 0) red[wid] = m;
    __syncthreads();
    m = red[0];
#pragma unroll
    for (int w = 1; w < 8; w++) m = fmaxf(m, red[w]);
    __syncthreads();

    float s = 0.f;
#pragma unroll
    for (int i = 0; i < 16; i++) { v[i] = expf(v[i] - m); s += v[i]; }
#pragma unroll
    for (int o = 16; o > 0; o >>= 1) s += __shfl_xor_sync(0xFFFFFFFFu, s, o);
    if (lane == 0) red[wid] = s;
    __syncthreads();
    s = red[0];
#pragma unroll
    for (int w = 1; w < 8; w++) s += red[w];

    const float inv = 1.f / s;
#pragma unroll
    for (int i = 0; i < 16; i++) p[tid + i * 256] = v[i] * inv;
}

// ---------------------------------------------------------------------------
// out = LayerNorm(A + B) * g + be   (one block of 128 threads per row of 512)
// ---------------------------------------------------------------------------
__global__ __launch_bounds__(128) void add_ln_kernel(
    const float* __restrict__ A, const float* __restrict__ Bv,
    const float* __restrict__ g, const float* __restrict__ be,
    float* __restrict__ out)
{
    const long row = blockIdx.x;
    const int tid = threadIdx.x;
    const int lane = tid & 31, wid = tid >> 5;
    __shared__ float red[4];

    float4 a = *(const float4*)(A + row * DM + tid * 4);
    float4 b = *(const float4*)(Bv + row * DM + tid * 4);
    float x0 = a.x + b.x, x1 = a.y + b.y, x2 = a.z + b.z, x3 = a.w + b.w;

    float s = x0 + x1 + x2 + x3;
#pragma unroll
    for (int o = 16; o > 0; o >>= 1) s += __shfl_xor_sync(0xFFFFFFFFu, s, o);
    if (lane == 0) red[wid] = s;
    __syncthreads();
    s = red[0] + red[1] + red[2] + red[3];
    const float mu = s * (1.0f / DM);
    __syncthreads();

    const float d0 = x0 - mu, d1 = x1 - mu, d2 = x2 - mu, d3 = x3 - mu;
    float vs = d0 * d0 + d1 * d1 + d2 * d2 + d3 * d3;
#pragma unroll
    for (int o = 16; o > 0; o >>= 1) vs += __shfl_xor_sync(0xFFFFFFFFu, vs, o);
    if (lane == 0) red[wid] = vs;
    __syncthreads();
    vs = red[0] + red[1] + red[2] + red[3];
    const float rs = rsqrtf(vs * (1.0f / DM) + 1e-5f);

    float4 gg = *(const float4*)(g + tid * 4);
    float4 bb = *(const float4*)(be + tid * 4);
    float4 o4;
    o4.x = d0 * rs * gg.x + bb.x;
    o4.y = d1 * rs * gg.y + bb.y;
    o4.z = d2 * rs * gg.z + bb.z;
    o4.w = d3 * rs * gg.w + bb.w;
    *(float4*)(out + row * DM + tid * 4) = o4;
}

// ---------------------------------------------------------------------------
// Host launcher
// ---------------------------------------------------------------------------
extern "C" void kernel_launch(void* const* d_in, const int* in_sizes, int n_in,
                              void* d_out, int out_size)
{
    const float* x   = (const float*)d_in[0];
    const void*  am  = d_in[1];
    const void*  kpm = d_in[2];
    const float* Wq  = (const float*)d_in[3];
    const float* Wk  = (const float*)d_in[4];
    const float* Wv  = (const float*)d_in[5];
    const float* Wf  = (const float*)d_in[6];
    const float* bfp = (const float*)d_in[7];
    const float* g1  = (const float*)d_in[8];
    const float* b1  = (const float*)d_in[9];
    const float* g2  = (const float*)d_in[10];
    const float* b2  = (const float*)d_in[11];
    float* out = (float*)d_out;

    void *pq, *pk, *pv, *ph, *pz, *psc;
    cudaGetSymbolAddress(&pq, g_q);
    cudaGetSymbolAddress(&pk, g_k);
    cudaGetSymbolAddress(&pv, g_v);
    cudaGetSymbolAddress(&ph, g_h);
    cudaGetSymbolAddress(&pz, g_z);
    cudaGetSymbolAddress(&psc, g_scores);

    // 0) mask dtype detection
    detect_mask_kernel<<<1, 32>>>(am);

    // 1) q = x @ Wq, k = x @ Wk  (M=16384, N=32, K=512)
    gemm_f32<<<dim3(1, BS_ROWS / 64, 1), 256>>>(x, Wq, (float*)pq, BS_ROWS, DK, DM, 0, 0, 0, nullptr, 0);
    gemm_f32<<<dim3(1, BS_ROWS / 64, 1), 256>>>(x, Wk, (float*)pk, BS_ROWS, DK, DM, 0, 0, 0, nullptr, 0);

    // 2) per-row c_i and pad flags
    rowstats_kernel<<<BS_ROWS / 256, 256>>>(kpm);

    // 3) v = x @ Wv  (M=16384, N=512, K=512)
    gemm_f32<<<dim3(DM / 64, BS_ROWS / 64, 1), 256>>>(x, Wv, (float*)pv, BS_ROWS, DM, DM, 0, 0, 0, nullptr, 0);

    // 4) masked scores (fp32, exact handling of the -1e24 key masking quirk)
    scores_kernel<<<dim3(SEQ / 64, SEQ / 64, BATCH), 256>>>(am);

    // 5) softmax rows in place
    softmax_kernel<<<dim3(SEQ, BATCH), 256>>>();

    // 6) h = P @ V  (batched: M=4096, N=512, K=4096)
    gemm_f32<<<dim3(DM / 64, SEQ / 64, BATCH), 256>>>(
        (const float*)psc, (const float*)pv, (float*)ph,
        SEQ, DM, SEQ, (long)SEQ * SEQ, (long)SEQ * DM, (long)SEQ * DM, nullptr, 0);

    // 7) z = LN(x + h)
    add_ln_kernel<<<BS_ROWS, 128>>>(x, (const float*)ph, g1, b1, (float*)pz);

    // 8) y = leaky_relu(z @ Wf + bf)  -> reuse g_h
    gemm_f32<<<dim3(DM / 64, BS_ROWS / 64, 1), 256>>>(
        (const float*)pz, Wf, (float*)ph, BS_ROWS, DM, DM, 0, 0, 0, bfp, 1);

    // 9) out = LN(z + y)
    add_ln_kernel<<<BS_ROWS, 128>>>((const float*)pz, (const float*)ph, g2, b2, out);
}

// round 3
// speedup vs baseline: 3.4508x; 3.4508x over previous
#include <cuda_runtime.h>
#include <cuda_bf16.h>
#include <cstdint>

// ---------------------------------------------------------------------------
// Problem constants
// ---------------------------------------------------------------------------
#define BATCH 4
#define SEQ   4096
#define DM    512
#define DK    32
#define BS_ROWS (BATCH * SEQ)           // 16384
static const float INV_DK = 0.17677669529663687f;   // 1/sqrt(32)
#define NINF_F (-1e24f)

// ---------------------------------------------------------------------------
// Scratch (static device globals; allocations are forbidden)
// ---------------------------------------------------------------------------
static __device__ int   g_mask_mode;
static __device__ float g_q[BS_ROWS * DK];
static __device__ float g_k[BS_ROWS * DK];
static __device__ float g_crow[BS_ROWS];
static __device__ float g_padf[BS_ROWS];
static __device__ float g_h[(size_t)BS_ROWS * DM];           // 32 MB
static __device__ float g_z[(size_t)BS_ROWS * DM];           // 32 MB
static __device__ float g_scores[(size_t)BATCH * SEQ * SEQ]; // 256 MB
static __device__ __nv_bfloat16 g_p[(size_t)BATCH * SEQ * SEQ];   // 128 MB probs
static __device__ __nv_bfloat16 g_x16[(size_t)BS_ROWS * DM];      // x in bf16
static __device__ __nv_bfloat16 g_vt[(size_t)BATCH * DM * SEQ];   // V^T bf16 per batch
static __device__ __nv_bfloat16 g_zhi[(size_t)BS_ROWS * DM];
static __device__ __nv_bfloat16 g_zlo[(size_t)BS_ROWS * DM];
static __device__ __nv_bfloat16 g_wvt[DM * DM];                   // Wv^T bf16
static __device__ __nv_bfloat16 g_wfhi[DM * DM];                  // Wf^T hi
static __device__ __nv_bfloat16 g_wflo[DM * DM];                  // Wf^T lo

// ---------------------------------------------------------------------------
// PTX helpers (generic compute_103 safe: cp.async / ldmatrix / mma.sync only)
// ---------------------------------------------------------------------------
__device__ __forceinline__ uint32_t smem_u32(const void* p) {
    uint32_t a;
    asm("{ .reg .u64 t; cvta.to.shared.u64 t, %1; cvt.u32.u64 %0, t; }" : "=r"(a) : "l"(p));
    return a;
}
__device__ __forceinline__ void cp16(uint32_t dst, const void* src) {
    asm volatile("cp.async.cg.shared.global [%0], [%1], 16;" :: "r"(dst), "l"(src));
}
#define CP_COMMIT()  asm volatile("cp.async.commit_group;" ::: "memory")
#define CP_WAIT(n)   asm volatile("cp.async.wait_group %0;" :: "n"(n) : "memory")

__device__ __forceinline__ void ldsm_x4(uint32_t& r0, uint32_t& r1, uint32_t& r2,
                                        uint32_t& r3, uint32_t addr) {
    asm volatile("ldmatrix.sync.aligned.m8n8.x4.shared.b16 {%0,%1,%2,%3}, [%4];"
                 : "=r"(r0), "=r"(r1), "=r"(r2), "=r"(r3) : "r"(addr));
}
__device__ __forceinline__ void mma16816(float* c, const uint32_t* a,
                                         uint32_t b0, uint32_t b1) {
    asm volatile(
        "mma.sync.aligned.m16n8k16.row.col.f32.bf16.bf16.f32 "
        "{%0,%1,%2,%3}, {%4,%5,%6,%7}, {%8,%9}, {%0,%1,%2,%3};"
        : "+f"(c[0]), "+f"(c[1]), "+f"(c[2]), "+f"(c[3])
        : "r"(a[0]), "r"(a[1]), "r"(a[2]), "r"(a[3]), "r"(b0), "r"(b1));
}
#define SW128(off) ((off) ^ (((off) >> 3) & 0x70))

// ---------------------------------------------------------------------------
// Mask dtype handling
// ---------------------------------------------------------------------------
__device__ __forceinline__ bool mask_true(const void* p, long i, int mode)
{
    if (mode == 0) return ((const float*)p)[i] != 0.0f;
    if (mode == 1) return ((const int*)p)[i] != 0;
    if (mode == 2) return ((const unsigned short*)p)[i] != 0;
    return ((const unsigned char*)p)[i] != 0;
}

__global__ void detect_mask_kernel(const void* __restrict__ am)
{
    if (threadIdx.x != 0 || blockIdx.x != 0) return;
    const unsigned int* w = (const unsigned int*)am;
    bool f32ok = true, i32ok = true, bf16ok = true;
    for (int i = 0; i < 1024; i++) {
        unsigned int v = w[i];
        if (!(v == 0u || v == 0x3F800000u)) f32ok = false;
        if (!(v == 0u || v == 1u)) i32ok = false;
        unsigned int h0 = v & 0xFFFFu, h1 = v >> 16;
        if (!((h0 == 0u || h0 == 0x3F80u) && (h1 == 0u || h1 == 0x3F80u))) bf16ok = false;
    }
    g_mask_mode = f32ok ? 0 : (i32ok ? 1 : (bf16ok ? 2 : 3));
}

// ---------------------------------------------------------------------------
// fp32 GEMM (q/k projections, N=32)
// ---------------------------------------------------------------------------
__global__ __launch_bounds__(256) void gemm_f32(
    const float* __restrict__ A, const float* __restrict__ B, float* __restrict__ C,
    int M, int N, int K)
{
    __shared__ float As[16][64];
    __shared__ float Bs[16][64];
    const int tid = threadIdx.x;
    const int m0 = blockIdx.y * 64, n0 = blockIdx.x * 64;
    const int tx = tid & 15, ty = tid >> 4;
    const int arow = tid >> 2, ac = (tid & 3) * 4;
    const int brow = tid >> 4, bc = (tid & 15) * 4;

    float acc[4][4] = {};
    for (int k0 = 0; k0 < K; k0 += 16) {
        float4 av = *(const float4*)(A + (long)(m0 + arow) * K + k0 + ac);
        As[ac + 0][arow] = av.x; As[ac + 1][arow] = av.y;
        As[ac + 2][arow] = av.z; As[ac + 3][arow] = av.w;
        float4 bv;
        if (n0 + bc + 3 < N) bv = *(const float4*)(B + (long)(k0 + brow) * N + n0 + bc);
        else {
            bv.x = (n0 + bc + 0 < N) ? B[(long)(k0 + brow) * N + n0 + bc + 0] : 0.f;
            bv.y = (n0 + bc + 1 < N) ? B[(long)(k0 + brow) * N + n0 + bc + 1] : 0.f;
            bv.z = (n0 + bc + 2 < N) ? B[(long)(k0 + brow) * N + n0 + bc + 2] : 0.f;
            bv.w = (n0 + bc + 3 < N) ? B[(long)(k0 + brow) * N + n0 + bc + 3] : 0.f;
        }
        *(float4*)&Bs[brow][bc] = bv;
        __syncthreads();
#pragma unroll
        for (int kk = 0; kk < 16; kk++) {
            float4 a = *(const float4*)&As[kk][ty * 4];
            float4 b = *(const float4*)&Bs[kk][tx * 4];
            acc[0][0] += a.x * b.x; acc[0][1] += a.x * b.y; acc[0][2] += a.x * b.z; acc[0][3] += a.x * b.w;
            acc[1][0] += a.y * b.x; acc[1][1] += a.y * b.y; acc[1][2] += a.y * b.z; acc[1][3] += a.y * b.w;
            acc[2][0] += a.z * b.x; acc[2][1] += a.z * b.y; acc[2][2] += a.z * b.z; acc[2][3] += a.z * b.w;
            acc[3][0] += a.w * b.x; acc[3][1] += a.w * b.y; acc[3][2] += a.w * b.z; acc[3][3] += a.w * b.w;
        }
        __syncthreads();
    }
#pragma unroll
    for (int i = 0; i < 4; i++) {
        const int m = m0 + ty * 4 + i;
#pragma unroll
        for (int j = 0; j < 4; j++) {
            const int n = n0 + tx * 4 + j;
            if (n < N) C[(long)m * N + n] = acc[i][j];
        }
    }
}

// ---------------------------------------------------------------------------
// Converts
// ---------------------------------------------------------------------------
__global__ void conv_x_bf16_kernel(const float* __restrict__ x)
{
    const long i = ((long)blockIdx.x * blockDim.x + threadIdx.x) * 4;
    float4 v = *(const float4*)(x + i);
    __nv_bfloat16 o[4] = { __float2bfloat16(v.x), __float2bfloat16(v.y),
                           __float2bfloat16(v.z), __float2bfloat16(v.w) };
    *(uint2*)(g_x16 + i) = *(uint2*)o;
}

// T[n][k] = W[k][n] in bf16 (optionally hi/lo split). W is [512,512].
__global__ void wtrans_kernel(const float* __restrict__ W,
                              __nv_bfloat16* __restrict__ Thi,
                              __nv_bfloat16* __restrict__ Tlo)
{
    __shared__ float tile[32][33];
    const int k0 = blockIdx.y * 32, n0 = blockIdx.x * 32;
    tile[threadIdx.y][threadIdx.x] = W[(long)(k0 + threadIdx.y) * DM + n0 + threadIdx.x];
    __syncthreads();
    const float v = tile[threadIdx.x][threadIdx.y];   // W[k0+tx][n0+ty]
    const long o = (long)(n0 + threadIdx.y) * DM + k0 + threadIdx.x;
    const __nv_bfloat16 hi = __float2bfloat16(v);
    Thi[o] = hi;
    if (Tlo) Tlo[o] = __float2bfloat16(v - __bfloat162float(hi));
}

// ---------------------------------------------------------------------------
// rowstats: c_i = rowsum(q) * (-1e24) * inv_dk ; pad flag
// ---------------------------------------------------------------------------
__global__ void rowstats_kernel(const void* __restrict__ pad)
{
    const int row = blockIdx.x * blockDim.x + threadIdx.x;
    if (row >= BS_ROWS) return;
    float s = 0.f;
#pragma unroll
    for (int d = 0; d < DK; d++) s += g_q[row * DK + d];
    g_crow[row] = s * NINF_F * INV_DK;
    g_padf[row] = mask_true(pad, row, g_mask_mode) ? 1.f : 0.f;
}

// ---------------------------------------------------------------------------
// Masked scores (fp32, exact knife-edge handling)
// ---------------------------------------------------------------------------
__global__ __launch_bounds__(256) void scores_kernel(const void* __restrict__ am)
{
    const int b = blockIdx.z;
    const int q0 = blockIdx.y * 64, k0 = blockIdx.x * 64;
    __shared__ float Qt[DK][64];
    __shared__ float Kt[DK][64];
    __shared__ float Cs[64];
    __shared__ float Ps[64];
    const int tid = threadIdx.x;
    const long rowq = (long)b * SEQ + q0;
    const long rowk = (long)b * SEQ + k0;

    for (int i = tid; i < 512; i += 256) {
        const int r = i >> 3, c = (i & 7) * 4;
        float4 v = *(const float4*)(g_q + (rowq + r) * DK + c);
        Qt[c + 0][r] = v.x; Qt[c + 1][r] = v.y; Qt[c + 2][r] = v.z; Qt[c + 3][r] = v.w;
        float4 w = *(const float4*)(g_k + (rowk + r) * DK + c);
        Kt[c + 0][r] = w.x; Kt[c + 1][r] = w.y; Kt[c + 2][r] = w.z; Kt[c + 3][r] = w.w;
    }
    if (tid < 64) { Cs[tid] = g_crow[rowq + tid]; Ps[tid] = g_padf[rowk + tid]; }
    __syncthreads();

    const int tx = tid & 15, ty = tid >> 4;
    float acc[4][4] = {};
#pragma unroll
    for (int kk = 0; kk < DK; kk++) {
        float4 a = *(const float4*)&Qt[kk][ty * 4];
        float4 b2 = *(const float4*)&Kt[kk][tx * 4];
        acc[0][0] += a.x * b2.x; acc[0][1] += a.x * b2.y; acc[0][2] += a.x * b2.z; acc[0][3] += a.x * b2.w;
        acc[1][0] += a.y * b2.x; acc[1][1] += a.y * b2.y; acc[1][2] += a.y * b2.z; acc[1][3] += a.y * b2.w;
        acc[2][0] += a.z * b2.x; acc[2][1] += a.z * b2.y; acc[2][2] += a.z * b2.z; acc[2][3] += a.z * b2.w;
        acc[3][0] += a.w * b2.x; acc[3][1] += a.w * b2.y; acc[3][2] += a.w * b2.z; acc[3][3] += a.w * b2.w;
    }

    const int mode = g_mask_mode;
#pragma unroll
    for (int i = 0; i < 4; i++) {
        const int qi = q0 + ty * 4 + i;
        const long base = ((long)b * SEQ + qi) * SEQ;
        const float ci = Cs[ty * 4 + i];
#pragma unroll
        for (int j = 0; j < 4; j++) {
            const int kj = k0 + tx * 4 + j;
            float s = acc[i][j] * INV_DK;
            if (Ps[tx * 4 + j] != 0.f) s = ci;
            if (mask_true(am, base + kj, mode)) s = NINF_F;
            g_scores[base + kj] = s;
        }
    }
}

// ---------------------------------------------------------------------------
// Row softmax: read fp32 scores, write bf16 probs
// ---------------------------------------------------------------------------
__global__ __launch_bounds__(256) void softmax_kernel()
{
    const long row = (long)blockIdx.y * SEQ + blockIdx.x;
    const float* p = g_scores + row * SEQ;
    __nv_bfloat16* po = g_p + row * SEQ;
    const int tid = threadIdx.x;
    const int lane = tid & 31, wid = tid >> 5;
    __shared__ float red[8];

    float v[16];
#pragma unroll
    for (int i = 0; i < 16; i++) v[i] = p[tid + i * 256];
    float m = -3.4e38f;
#pragma unroll
    for (int i = 0; i < 16; i++) m = fmaxf(m, v[i]);
#pragma unroll
    for (int o = 16; o > 0; o >>= 1) m = fmaxf(m, __shfl_xor_sync(0xFFFFFFFFu, m, o));
    if (lane == 0) red[wid] = m;
    __syncthreads();
    m = red[0];
#pragma unroll
    for (int w = 1; w < 8; w++) m = fmaxf(m, red[w]);
    __syncthreads();

    float s = 0.f;
#pragma unroll
    for (int i = 0; i < 16; i++) { v[i] = expf(v[i] - m); s += v[i]; }
#pragma unroll
    for (int o = 16; o > 0; o >>= 1) s += __shfl_xor_sync(0xFFFFFFFFu, s, o);
    if (lane == 0) red[wid] = s;
    __syncthreads();
    s = red[0];
#pragma unroll
    for (int w = 1; w < 8; w++) s += red[w];

    const float inv = 1.f / s;
#pragma unroll
    for (int i = 0; i < 16; i++) po[tid + i * 256] = __float2bfloat16(v[i] * inv);
}

// ---------------------------------------------------------------------------
// out = LayerNorm(A + B); optionally also emit bf16 hi/lo split of out
// ---------------------------------------------------------------------------
__global__ __launch_bounds__(128) void add_ln_kernel(
    const float* __restrict__ A, const float* __restrict__ Bv,
    const float* __restrict__ g, const float* __restrict__ be,
    float* __restrict__ out, __nv_bfloat16* __restrict__ ohi,
    __nv_bfloat16* __restrict__ olo)
{
    const long row = blockIdx.x;
    const int tid = threadIdx.x;
    const int lane = tid & 31, wid = tid >> 5;
    __shared__ float red[4];

    float4 a = *(const float4*)(A + row * DM + tid * 4);
    float4 b = *(const float4*)(Bv + row * DM + tid * 4);
    float x0 = a.x + b.x, x1 = a.y + b.y, x2 = a.z + b.z, x3 = a.w + b.w;

    float s = x0 + x1 + x2 + x3;
#pragma unroll
    for (int o = 16; o > 0; o >>= 1) s += __shfl_xor_sync(0xFFFFFFFFu, s, o);
    if (lane == 0) red[wid] = s;
    __syncthreads();
    s = red[0] + red[1] + red[2] + red[3];
    const float mu = s * (1.0f / DM);
    __syncthreads();

    const float d0 = x0 - mu, d1 = x1 - mu, d2 = x2 - mu, d3 = x3 - mu;
    float vs = d0 * d0 + d1 * d1 + d2 * d2 + d3 * d3;
#pragma unroll
    for (int o = 16; o > 0; o >>= 1) vs += __shfl_xor_sync(0xFFFFFFFFu, vs, o);
    if (lane == 0) red[wid] = vs;
    __syncthreads();
    vs = red[0] + red[1] + red[2] + red[3];
    const float rs = rsqrtf(vs * (1.0f / DM) + 1e-5f);

    float4 gg = *(const float4*)(g + tid * 4);
    float4 bb = *(const float4*)(be + tid * 4);
    float o4[4];
    o4[0] = d0 * rs * gg.x + bb.x;
    o4[1] = d1 * rs * gg.y + bb.y;
    o4[2] = d2 * rs * gg.z + bb.z;
    o4[3] = d3 * rs * gg.w + bb.w;
    *(float4*)(out + row * DM + tid * 4) = *(float4*)o4;
    if (ohi) {
        __nv_bfloat16 hi[4], lo[4];
#pragma unroll
        for (int j = 0; j < 4; j++) {
            hi[j] = __float2bfloat16(o4[j]);
            lo[j] = __float2bfloat16(o4[j] - __bfloat162float(hi[j]));
        }
        *(uint2*)(ohi + row * DM + tid * 4) = *(uint2*)hi;
        *(uint2*)(olo + row * DM + tid * 4) = *(uint2*)lo;
    }
}

// ---------------------------------------------------------------------------
// bf16 tensor-core GEMM via mma.sync (generic compute_103 safe).
//   C[m][n] = sum_p sum_k Ap[m][k] * Bp[n][k]   (A, B K-major bf16)
// BM=BN=128, BK=64, 256 threads (8 warps, 64x32 warp tiles), double-buffered
// cp.async stages, SW128 swizzle, ldmatrix + mma.sync.m16n8k16 (fp32 accum).
// mode 0: fp32 row-major store      [P@V -> h]
// mode 1: bf16 transposed store via SMEM restage [(b*DM+n)*SEQ + s]
// mode 2: bias + leaky_relu fp32    [FFN]
// ---------------------------------------------------------------------------
#define GM_STAGE 32768                    // A 16KB + B 16KB
#define GM_SMEM  (2 * GM_STAGE)           // 64 KB

__global__ __launch_bounds__(256) void gemm_mma(
    const __nv_bfloat16* __restrict__ A0, const __nv_bfloat16* __restrict__ A1,
    const __nv_bfloat16* __restrict__ A2,
    const __nv_bfloat16* __restrict__ B0, const __nv_bfloat16* __restrict__ B1,
    const __nv_bfloat16* __restrict__ B2,
    int npass, int Ktot, long batchA, long batchB, long batchC,
    float* __restrict__ C, __nv_bfloat16* __restrict__ Ct,
    const float* __restrict__ bias, int mode, int ldc)
{
    extern __shared__ char smem[];
    const uint32_t sb = smem_u32(smem);
    const int tid = threadIdx.x;
    const int lane = tid & 31, wid = tid >> 5;
    const int wr = wid >> 2, wc = wid & 3;         // warp tile: rows 64*wr, cols 32*wc
    const int m0 = blockIdx.y * 128, n0 = blockIdx.x * 128;
    const long zb = blockIdx.z;

    const __nv_bfloat16* Ap[3] = { A0 ? A0 + zb * batchA : nullptr,
                                   A1 ? A1 + zb * batchA : nullptr,
                                   A2 ? A2 + zb * batchA : nullptr };
    const __nv_bfloat16* Bp[3] = { B0 ? B0 + zb * batchB : nullptr,
                                   B1 ? B1 + zb * batchB : nullptr,
                                   B2 ? B2 + zb * batchB : nullptr };

    const int kc = Ktot >> 6;               // chunks per pass
    const int nch = npass * kc;

    // per-thread load slots: 4 x 16B for A, 4 x 16B for B
    const int lrow = tid >> 3, lc = (tid & 7);       // lrow 0..31 step, lc*16 bytes

    // ---- load chunk c into buffer buf ----
    auto load_chunk = [&](int c, int buf) {
        const int p = c / kc;
        const int k0 = (c - p * kc) << 6;
        const __nv_bfloat16* A = Ap[p];
        const __nv_bfloat16* B = Bp[p];
        const uint32_t sa = sb + buf * GM_STAGE;
        const uint32_t sbB = sa + 16384;
#pragma unroll
        for (int it = 0; it < 4; it++) {
            const int row = lrow + it * 32;
            cp16(sa + SW128(row * 128 + lc * 16), A + (long)(m0 + row) * Ktot + k0 + lc * 8);
            cp16(sbB + SW128(row * 128 + lc * 16), B + (long)(n0 + row) * Ktot + k0 + lc * 8);
        }
        CP_COMMIT();
    };

    float acc[4][4][4] = {};

    load_chunk(0, 0);
    for (int c = 0; c < nch; c++) {
        if (c + 1 < nch) { load_chunk(c + 1, (c + 1) & 1); CP_WAIT(1); }
        else             { CP_WAIT(0); }
        __syncthreads();

        const uint32_t sa = sb + (c & 1) * GM_STAGE;
        const uint32_t sbB = sa + 16384;
#pragma unroll
        for (int ks = 0; ks < 4; ks++) {
            uint32_t a[4][4];
#pragma unroll
            for (int mi = 0; mi < 4; mi++) {
                const int mr = wr * 64 + mi * 16 + (lane & 15);
                ldsm_x4(a[mi][0], a[mi][1], a[mi][2], a[mi][3],
                        sa + SW128(mr * 128 + ks * 32 + ((lane >> 4) << 4)));
            }
            uint32_t b[2][4];
#pragma unroll
            for (int j = 0; j < 2; j++) {
                const int nr = wc * 32 + j * 16 + (lane & 7) + ((lane >> 4) << 3);
                ldsm_x4(b[j][0], b[j][1], b[j][2], b[j][3],
                        sbB + SW128(nr * 128 + ks * 32 + (((lane >> 3) & 1) << 4)));
            }
#pragma unroll
            for (int mi = 0; mi < 4; mi++)
#pragma unroll
                for (int nj = 0; nj < 4; nj++)
                    mma16816(acc[mi][nj], a[mi],
                             b[nj >> 1][(nj & 1) * 2], b[nj >> 1][(nj & 1) * 2 + 1]);
        }
        __syncthreads();
    }

    // ---- epilogue ----
    const int crow = lane >> 2, ccol = (lane & 3) * 2;
    if (mode == 1) {
        // restage as [n_local][m_local] bf16, then coalesced transposed store
        __nv_bfloat16* st = (__nv_bfloat16*)smem;
#pragma unroll
        for (int mi = 0; mi < 4; mi++) {
#pragma unroll
            for (int nj = 0; nj < 4; nj++) {
                const int ml = wr * 64 + mi * 16 + crow;
                const int cl = wc * 32 + nj * 8 + ccol;
                st[(cl + 0) * 128 + ml]     = __float2bfloat16(acc[mi][nj][0]);
                st[(cl + 1) * 128 + ml]     = __float2bfloat16(acc[mi][nj][1]);
                st[(cl + 0) * 128 + ml + 8] = __float2bfloat16(acc[mi][nj][2]);
                st[(cl + 1) * 128 + ml + 8] = __float2bfloat16(acc[mi][nj][3]);
            }
        }
        __syncthreads();
        const long bb = m0 >> 12;           // batch index of this row block
        const long s0 = m0 & 4095;
#pragma unroll
        for (int it = 0; it < 8; it++) {
            const int i = tid + it * 256;
            const int row = i >> 4, seg = i & 15;
            *(uint4*)(Ct + ((bb * DM) + n0 + row) * SEQ + s0 + seg * 8) =
                *(uint4*)(st + row * 128 + seg * 8);
        }
    } else if (mode == 0) {
        float* Cb = C + zb * batchC;
#pragma unroll
        for (int mi = 0; mi < 4; mi++) {
#pragma unroll
            for (int nj = 0; nj < 4; nj++) {
                const long mr = m0 + wr * 64 + mi * 16 + crow;
                const int cl = n0 + wc * 32 + nj * 8 + ccol;
                *(float2*)(Cb + mr * ldc + cl)       = make_float2(acc[mi][nj][0], acc[mi][nj][1]);
                *(float2*)(Cb + (mr + 8) * ldc + cl) = make_float2(acc[mi][nj][2], acc[mi][nj][3]);
            }
        }
    } else {
#pragma unroll
        for (int mi = 0; mi < 4; mi++) {
#pragma unroll
            for (int nj = 0; nj < 4; nj++) {
                const long mr = m0 + wr * 64 + mi * 16 + crow;
                const int cl = n0 + wc * 32 + nj * 8 + ccol;
                const float b0 = bias[cl], b1 = bias[cl + 1];
                float v0 = acc[mi][nj][0] + b0, v1 = acc[mi][nj][1] + b1;
                float v2 = acc[mi][nj][2] + b0, v3 = acc[mi][nj][3] + b1;
                v0 = (v0 > 0.f) ? v0 : 0.01f * v0;
                v1 = (v1 > 0.f) ? v1 : 0.01f * v1;
                v2 = (v2 > 0.f) ? v2 : 0.01f * v2;
                v3 = (v3 > 0.f) ? v3 : 0.01f * v3;
                *(float2*)(C + mr * ldc + cl)       = make_float2(v0, v1);
                *(float2*)(C + (mr + 8) * ldc + cl) = make_float2(v2, v3);
            }
        }
    }
}

// ---------------------------------------------------------------------------
// Host launcher
// ---------------------------------------------------------------------------
extern "C" void kernel_launch(void* const* d_in, const int* in_sizes, int n_in,
                              void* d_out, int out_size)
{
    const float* x   = (const float*)d_in[0];
    const void*  am  = d_in[1];
    const void*  kpm = d_in[2];
    const float* Wq  = (const float*)d_in[3];
    const float* Wk  = (const float*)d_in[4];
    const float* Wv  = (const float*)d_in[5];
    const float* Wf  = (const float*)d_in[6];
    const float* bfp = (const float*)d_in[7];
    const float* g1  = (const float*)d_in[8];
    const float* b1  = (const float*)d_in[9];
    const float* g2  = (const float*)d_in[10];
    const float* b2  = (const float*)d_in[11];
    float* out = (float*)d_out;

    void *pq, *pk, *ph, *pz, *pp, *px16, *pvt, *pzhi, *pzlo, *pwvt, *pwfhi, *pwflo;
    cudaGetSymbolAddress(&pq, g_q);
    cudaGetSymbolAddress(&pk, g_k);
    cudaGetSymbolAddress(&ph, g_h);
    cudaGetSymbolAddress(&pz, g_z);
    cudaGetSymbolAddress(&pp, g_p);
    cudaGetSymbolAddress(&px16, g_x16);
    cudaGetSymbolAddress(&pvt, g_vt);
    cudaGetSymbolAddress(&pzhi, g_zhi);
    cudaGetSymbolAddress(&pzlo, g_zlo);
    cudaGetSymbolAddress(&pwvt, g_wvt);
    cudaGetSymbolAddress(&pwfhi, g_wfhi);
    cudaGetSymbolAddress(&pwflo, g_wflo);

    cudaFuncSetAttribute(gemm_mma, cudaFuncAttributeMaxDynamicSharedMemorySize, GM_SMEM);

    // 0) mask dtype detection + converts
    detect_mask_kernel<<<1, 32>>>(am);
    conv_x_bf16_kernel<<<(BS_ROWS * DM) / (256 * 4), 256>>>(x);
    wtrans_kernel<<<dim3(16, 16), dim3(32, 32)>>>(Wv, (__nv_bfloat16*)pwvt, nullptr);
    wtrans_kernel<<<dim3(16, 16), dim3(32, 32)>>>(Wf, (__nv_bfloat16*)pwfhi, (__nv_bfloat16*)pwflo);

    // 1) q,k projections (fp32 — protects the sign(rowsum(q)) knife edge)
    gemm_f32<<<dim3(1, BS_ROWS / 64), 256>>>(x, Wq, (float*)pq, BS_ROWS, DK, DM);
    gemm_f32<<<dim3(1, BS_ROWS / 64), 256>>>(x, Wk, (float*)pk, BS_ROWS, DK, DM);
    rowstats_kernel<<<BS_ROWS / 256, 256>>>(kpm);

    // 2) Vt = (x @ Wv)^T in bf16 (tensor cores, transposed store)
    gemm_mma<<<dim3(DM / 128, BS_ROWS / 128, 1), 256, GM_SMEM>>>(
        (const __nv_bfloat16*)px16, nullptr, nullptr,
        (const __nv_bfloat16*)pwvt, nullptr, nullptr,
        1, DM, 0, 0, 0, nullptr, (__nv_bfloat16*)pvt, nullptr, 1, 0);

    // 3) masked scores (fp32) + softmax -> bf16 probs
    scores_kernel<<<dim3(SEQ / 64, SEQ / 64, BATCH), 256>>>(am);
    softmax_kernel<<<dim3(SEQ, BATCH), 256>>>();

    // 4) h = P @ V (tensor cores, batched)
    gemm_mma<<<dim3(DM / 128, SEQ / 128, BATCH), 256, GM_SMEM>>>(
        (const __nv_bfloat16*)pp, nullptr, nullptr,
        (const __nv_bfloat16*)pvt, nullptr, nullptr,
        1, SEQ, (long)SEQ * SEQ, (long)DM * SEQ, (long)SEQ * DM,
        (float*)ph, nullptr, nullptr, 0, DM);

    // 5) z = LN(x + h), emit z_hi/z_lo bf16 split
    add_ln_kernel<<<BS_ROWS, 128>>>(x, (const float*)ph, g1, b1, (float*)pz,
                                    (__nv_bfloat16*)pzhi, (__nv_bfloat16*)pzlo);

    // 6) y = leaky(z @ Wf + bf) via 3-pass split-bf16 (tensor cores)
    gemm_mma<<<dim3(DM / 128, BS_ROWS / 128, 1), 256, GM_SMEM>>>(
        (const __nv_bfloat16*)pzhi, (const __nv_bfloat16*)pzlo, (const __nv_bfloat16*)pzhi,
        (const __nv_bfloat16*)pwfhi, (const __nv_bfloat16*)pwfhi, (const __nv_bfloat16*)pwflo,
        3, DM, 0, 0, 0, (float*)ph, nullptr, bfp, 2, DM);

    // 7) out = LN(z + y)
    add_ln_kernel<<<BS_ROWS, 128>>>((const float*)pz, (const float*)ph, g2, b2, out,
                                    nullptr, nullptr);
}